// round 1
// baseline (speedup 1.0000x reference)
#include <cuda_runtime.h>
#include <cuda_bf16.h>

#define N_MAX 100000

// ---------------- scratch (device globals; no allocation allowed) ----------
__device__ int   g_degp[N_MAX];
__device__ int   g_degn[N_MAX];
__device__ float g_dinvp[N_MAX];
__device__ float g_dinvn[N_MAX];

__device__ float g_hp1[N_MAX * 16];   // x @ W1p
__device__ float g_hn1[N_MAX * 16];   // x @ W1n
__device__ float g_ap1[N_MAX * 16];   // aggregated pos (init with self-loop term)
__device__ float g_an1[N_MAX * 16];   // aggregated neg

__device__ float g_hp2[N_MAX * 32];
__device__ float g_hn2[N_MAX * 32];
__device__ float g_ap2[N_MAX * 32];
__device__ float g_an2[N_MAX * 32];

// ---------------- helpers ---------------------------------------------------
__device__ __forceinline__ void red_add_v4(float* p, float a, float b, float c, float d) {
    asm volatile("red.global.add.v4.f32 [%0], {%1,%2,%3,%4};"
                 :: "l"(p), "f"(a), "f"(b), "f"(c), "f"(d) : "memory");
}

__device__ __forceinline__ float relu(float x) { return x > 0.f ? x : 0.f; }

// ---------------- kernels ---------------------------------------------------
__global__ void k_zero_deg(int n) {
    int i = blockIdx.x * blockDim.x + threadIdx.x;
    if (i < n) { g_degp[i] = 0; g_degn[i] = 0; }
}

// count dst occurrences for pos and neg edge lists in one grid
__global__ void k_count_deg(const int* __restrict__ ep, const int* __restrict__ en, int E) {
    int i = blockIdx.x * blockDim.x + threadIdx.x;
    if (i < E) {
        atomicAdd(&g_degp[ep[E + i]], 1);       // dst row of pos
    } else if (i < 2 * E) {
        atomicAdd(&g_degn[en[E + (i - E)]], 1); // dst row of neg
    }
}

__global__ void k_dinv(int n) {
    int i = blockIdx.x * blockDim.x + threadIdx.x;
    if (i < n) {
        g_dinvp[i] = rsqrtf((float)g_degp[i] + 1.0f);  // +1 self loop
        g_dinvn[i] = rsqrtf((float)g_degn[i] + 1.0f);
    }
}

// GEMM1: h = x[100k,128] @ [W1p | W1n] (128x16 each). Warp per node, lane = feature
// (lanes 0-15: pos, 16-31: neg). Also writes self-loop contribution into ap1/an1.
__global__ void k_gemm1(const float* __restrict__ x,
                        const float* __restrict__ W1p, const float* __restrict__ W1n,
                        int n) {
    __shared__ float sW[128 * 32];  // [k][lane]
    int tid = threadIdx.x;
    for (int idx = tid; idx < 128 * 32; idx += 256) {
        int k = idx >> 5, l = idx & 31;
        sW[idx] = (l < 16) ? W1p[k * 16 + l] : W1n[k * 16 + (l - 16)];
    }
    __syncthreads();

    int lane = tid & 31;
    int node = blockIdx.x * 8 + (tid >> 5);
    if (node >= n) return;

    const float4* xr = (const float4*)(x + (size_t)node * 128);
    float acc = 0.f;
#pragma unroll
    for (int k4 = 0; k4 < 32; k4++) {
        float4 xv = __ldg(&xr[k4]);
        int kb = k4 * 4;
        acc += xv.x * sW[(kb + 0) * 32 + lane];
        acc += xv.y * sW[(kb + 1) * 32 + lane];
        acc += xv.z * sW[(kb + 2) * 32 + lane];
        acc += xv.w * sW[(kb + 3) * 32 + lane];
    }
    int f = lane & 15;
    if (lane < 16) {
        float d = g_dinvp[node];
        g_hp1[node * 16 + f] = acc;
        g_ap1[node * 16 + f] = acc * d * d;   // self-loop term
    } else {
        float d = g_dinvn[node];
        g_hn1[node * 16 + f] = acc;
        g_an1[node * 16 + f] = acc * d * d;
    }
}

// Scatter layer 1: 16 features per edge. One thread per edge; pos half then neg half.
__global__ void k_scatter1(const int* __restrict__ ep, const int* __restrict__ en, int E) {
    int i = blockIdx.x * blockDim.x + threadIdx.x;
    const int* el;
    const float* dinv;
    const float* h;
    float* agg;
    int e;
    if (i < E)            { el = ep; dinv = g_dinvp; h = g_hp1; agg = g_ap1; e = i; }
    else if (i < 2 * E)   { el = en; dinv = g_dinvn; h = g_hn1; agg = g_an1; e = i - E; }
    else return;

    int src = el[e];
    int dst = el[E + e];
    float w = dinv[src] * dinv[dst];
    const float4* hs = (const float4*)(h + (size_t)src * 16);
    float* ad = agg + (size_t)dst * 16;
#pragma unroll
    for (int j = 0; j < 4; j++) {
        float4 v = __ldg(&hs[j]);
        red_add_v4(ad + j * 4, v.x * w, v.y * w, v.z * w, v.w * w);
    }
}

// GEMM2: computes h1 = relu(ap1+b1p) - relu(an1+b1n) on the fly, then
// h1[16] @ [W2p | W2n] (16x32 each). 64 threads per node (32 pos + 32 neg feats).
__global__ void k_gemm2(const float* __restrict__ W2p, const float* __restrict__ W2n,
                        const float* __restrict__ b1p, const float* __restrict__ b1n,
                        int n) {
    __shared__ float sW[16 * 64];   // [k][t64]
    __shared__ float sb1p[16], sb1n[16];
    int tid = threadIdx.x;
    for (int idx = tid; idx < 16 * 64; idx += 256) {
        int k = idx >> 6, l = idx & 63;
        sW[idx] = (l < 32) ? W2p[k * 32 + l] : W2n[k * 32 + (l - 32)];
    }
    if (tid < 16) { sb1p[tid] = b1p[tid]; sb1n[tid] = b1n[tid]; }
    __syncthreads();

    int t64 = tid & 63;
    int node = blockIdx.x * 4 + (tid >> 6);
    if (node >= n) return;

    const float* ap = g_ap1 + (size_t)node * 16;
    const float* an = g_an1 + (size_t)node * 16;
    float acc = 0.f;
#pragma unroll
    for (int k = 0; k < 16; k++) {
        float hv = relu(__ldg(&ap[k]) + sb1p[k]) - relu(__ldg(&an[k]) + sb1n[k]);
        acc += hv * sW[k * 64 + t64];
    }
    int f = t64 & 31;
    if (t64 < 32) {
        float d = g_dinvp[node];
        g_hp2[node * 32 + f] = acc;
        g_ap2[node * 32 + f] = acc * d * d;
    } else {
        float d = g_dinvn[node];
        g_hn2[node * 32 + f] = acc;
        g_an2[node * 32 + f] = acc * d * d;
    }
}

// Scatter layer 2: 32 features per edge.
__global__ void k_scatter2(const int* __restrict__ ep, const int* __restrict__ en, int E) {
    int i = blockIdx.x * blockDim.x + threadIdx.x;
    const int* el;
    const float* dinv;
    const float* h;
    float* agg;
    int e;
    if (i < E)            { el = ep; dinv = g_dinvp; h = g_hp2; agg = g_ap2; e = i; }
    else if (i < 2 * E)   { el = en; dinv = g_dinvn; h = g_hn2; agg = g_an2; e = i - E; }
    else return;

    int src = el[e];
    int dst = el[E + e];
    float w = dinv[src] * dinv[dst];
    const float4* hs = (const float4*)(h + (size_t)src * 32);
    float* ad = agg + (size_t)dst * 32;
#pragma unroll
    for (int j = 0; j < 8; j++) {
        float4 v = __ldg(&hs[j]);
        red_add_v4(ad + j * 4, v.x * w, v.y * w, v.z * w, v.w * w);
    }
}

// Epilogue: z = relu(ap2+b2p) - relu(an2+b2n); log_softmax over 32 classes.
// Warp per node, lane = class.
__global__ void k_final(const float* __restrict__ b2p, const float* __restrict__ b2n,
                        float* __restrict__ out, int n) {
    int tid  = threadIdx.x;
    int lane = tid & 31;
    int node = blockIdx.x * 8 + (tid >> 5);
    if (node >= n) return;

    float z = relu(g_ap2[node * 32 + lane] + __ldg(&b2p[lane]))
            - relu(g_an2[node * 32 + lane] + __ldg(&b2n[lane]));

    float m = z;
#pragma unroll
    for (int o = 16; o > 0; o >>= 1) m = fmaxf(m, __shfl_xor_sync(0xFFFFFFFF, m, o));
    float ex = expf(z - m);
    float s = ex;
#pragma unroll
    for (int o = 16; o > 0; o >>= 1) s += __shfl_xor_sync(0xFFFFFFFF, s, o);

    out[(size_t)node * 32 + lane] = z - m - logf(s);
}

// ---------------- launch ----------------------------------------------------
extern "C" void kernel_launch(void* const* d_in, const int* in_sizes, int n_in,
                              void* d_out, int out_size) {
    const float* x   = (const float*)d_in[0];
    const int*   ep  = (const int*)  d_in[1];
    const int*   en  = (const int*)  d_in[2];
    const float* W1p = (const float*)d_in[3];
    const float* b1p = (const float*)d_in[4];
    const float* W1n = (const float*)d_in[5];
    const float* b1n = (const float*)d_in[6];
    const float* W2p = (const float*)d_in[7];
    const float* b2p = (const float*)d_in[8];
    const float* W2n = (const float*)d_in[9];
    const float* b2n = (const float*)d_in[10];
    float* out = (float*)d_out;

    int n = in_sizes[0] / 128;     // 100000
    int E = in_sizes[1] / 2;       // 3200000

    int nb_n  = (n + 255) / 256;
    int nb_2e = (2 * E + 255) / 256;

    k_zero_deg <<<nb_n, 256>>>(n);
    k_count_deg<<<nb_2e, 256>>>(ep, en, E);
    k_dinv     <<<nb_n, 256>>>(n);
    k_gemm1    <<<(n + 7) / 8, 256>>>(x, W1p, W1n, n);
    k_scatter1 <<<nb_2e, 256>>>(ep, en, E);
    k_gemm2    <<<(n + 3) / 4, 256>>>(W2p, W2n, b1p, b1n, n);
    k_scatter2 <<<nb_2e, 256>>>(ep, en, E);
    k_final    <<<(n + 7) / 8, 256>>>(b2p, b2n, out, n);
}

// round 2
// speedup vs baseline: 1.4650x; 1.4650x over previous
#include <cuda_runtime.h>
#include <cuda_bf16.h>

#define N_MAX 100000
#define E_MAX 3200000

// ---------------- scratch (device globals; no allocation allowed) ----------
__device__ int   g_degp[N_MAX];
__device__ int   g_degn[N_MAX];
__device__ float g_dinvp[N_MAX];
__device__ float g_dinvn[N_MAX];

__device__ float g_wp[E_MAX];         // per-edge norm, pos (shared by both layers)
__device__ float g_wn[E_MAX];         // per-edge norm, neg

__device__ float g_hp1[N_MAX * 16];   // x @ W1p
__device__ float g_hn1[N_MAX * 16];   // x @ W1n
__device__ float g_ap1[N_MAX * 16];   // aggregated pos (init with self-loop term)
__device__ float g_an1[N_MAX * 16];   // aggregated neg

__device__ float g_hp2[N_MAX * 32];
__device__ float g_hn2[N_MAX * 32];
__device__ float g_ap2[N_MAX * 32];
__device__ float g_an2[N_MAX * 32];

// ---------------- helpers ---------------------------------------------------
__device__ __forceinline__ void red_add_v4(float* p, float a, float b, float c, float d) {
    asm volatile("red.global.add.v4.f32 [%0], {%1,%2,%3,%4};"
                 :: "l"(p), "f"(a), "f"(b), "f"(c), "f"(d) : "memory");
}

__device__ __forceinline__ float relu(float x) { return x > 0.f ? x : 0.f; }

// ---------------- kernels ---------------------------------------------------
__global__ void k_zero_deg(int n) {
    int i = blockIdx.x * blockDim.x + threadIdx.x;
    if (i < n) { g_degp[i] = 0; g_degn[i] = 0; }
}

__global__ void k_count_deg(const int* __restrict__ ep, const int* __restrict__ en, int E) {
    int i = blockIdx.x * blockDim.x + threadIdx.x;
    if (i < E) {
        atomicAdd(&g_degp[ep[E + i]], 1);
    } else if (i < 2 * E) {
        atomicAdd(&g_degn[en[E + (i - E)]], 1);
    }
}

__global__ void k_dinv(int n) {
    int i = blockIdx.x * blockDim.x + threadIdx.x;
    if (i < n) {
        g_dinvp[i] = rsqrtf((float)g_degp[i] + 1.0f);  // +1 self loop
        g_dinvn[i] = rsqrtf((float)g_degn[i] + 1.0f);
    }
}

// Precompute per-edge normalization weights (reused by both layers).
__global__ void k_norm(const int* __restrict__ ep, const int* __restrict__ en, int E) {
    int i = blockIdx.x * blockDim.x + threadIdx.x;
    if (i < E) {
        g_wp[i] = g_dinvp[ep[i]] * g_dinvp[ep[E + i]];
    } else if (i < 2 * E) {
        int e = i - E;
        g_wn[e] = g_dinvn[en[e]] * g_dinvn[en[E + e]];
    }
}

// GEMM1: h = x[100k,128] @ [W1p | W1n]. Warp processes 4 nodes; lane = output
// feature (0-15 pos, 16-31 neg). W transposed in smem ([feat][k], pad 132) so
// each LDS.128 serves 4 k's and is reused across 4 nodes (4x fewer LDS bytes).
// Also writes self-loop contribution into ap1/an1.
__global__ void k_gemm1(const float* __restrict__ x,
                        const float* __restrict__ W1p, const float* __restrict__ W1n,
                        int n) {
    __shared__ float sWt[32 * 132];
    int tid = threadIdx.x;
    for (int idx = tid; idx < 128 * 32; idx += 256) {
        int k = idx & 127, f = idx >> 7;
        sWt[f * 132 + k] = (f < 16) ? W1p[k * 16 + f] : W1n[k * 16 + (f - 16)];
    }
    __syncthreads();

    int lane = tid & 31;
    int nb = (blockIdx.x * 8 + (tid >> 5)) * 4;
    if (nb >= n) return;

    const float4* x0 = (const float4*)(x + (size_t)nb * 128);
    const float4* x1 = (nb + 1 < n) ? x0 + 32 : x0;
    const float4* x2 = (nb + 2 < n) ? x0 + 64 : x0;
    const float4* x3 = (nb + 3 < n) ? x0 + 96 : x0;

    float acc0 = 0.f, acc1 = 0.f, acc2 = 0.f, acc3 = 0.f;
#pragma unroll
    for (int k4 = 0; k4 < 32; k4++) {
        float4 w = *(const float4*)&sWt[lane * 132 + k4 * 4];
        float4 a = __ldg(&x0[k4]);
        float4 b = __ldg(&x1[k4]);
        float4 c = __ldg(&x2[k4]);
        float4 d = __ldg(&x3[k4]);
        acc0 += a.x * w.x + a.y * w.y + a.z * w.z + a.w * w.w;
        acc1 += b.x * w.x + b.y * w.y + b.z * w.z + b.w * w.w;
        acc2 += c.x * w.x + c.y * w.y + c.z * w.z + c.w * w.w;
        acc3 += d.x * w.x + d.y * w.y + d.z * w.z + d.w * w.w;
    }

    float accs[4] = {acc0, acc1, acc2, acc3};
    int f = lane & 15;
#pragma unroll
    for (int j = 0; j < 4; j++) {
        int node = nb + j;
        if (node >= n) break;
        if (lane < 16) {
            float d = g_dinvp[node];
            g_hp1[node * 16 + f] = accs[j];
            g_ap1[node * 16 + f] = accs[j] * d * d;
        } else {
            float d = g_dinvn[node];
            g_hn1[node * 16 + f] = accs[j];
            g_an1[node * 16 + f] = accs[j] * d * d;
        }
    }
}

// Scatter layer 1: 4 lanes (one float4 each) per edge -> 8 edges/warp.
// One gather instruction touches 8 lines instead of 32 sector-accesses.
__global__ void k_scatter1(const int* __restrict__ ep, const int* __restrict__ en, int E) {
    int i = blockIdx.x * blockDim.x + threadIdx.x;
    int slot = i >> 2, q = i & 3;
    const int* el; const float* wt; const float* h; float* agg; int e;
    if (slot < E)          { el = ep; wt = g_wp; h = g_hp1; agg = g_ap1; e = slot; }
    else if (slot < 2 * E) { el = en; wt = g_wn; h = g_hn1; agg = g_an1; e = slot - E; }
    else return;

    int src = __ldg(&el[e]);
    int dst = __ldg(&el[E + e]);
    float w = __ldg(&wt[e]);
    float4 v = __ldg(((const float4*)h) + (size_t)src * 4 + q);
    red_add_v4(agg + (size_t)dst * 16 + q * 4, v.x * w, v.y * w, v.z * w, v.w * w);
}

// GEMM2: h1 = relu(ap1+b1p) - relu(an1+b1n) on the fly, then h1 @ [W2p | W2n].
// 64 threads per node (32 pos feats + 32 neg feats).
__global__ void k_gemm2(const float* __restrict__ W2p, const float* __restrict__ W2n,
                        const float* __restrict__ b1p, const float* __restrict__ b1n,
                        int n) {
    __shared__ float sW[16 * 64];
    __shared__ float sb1p[16], sb1n[16];
    int tid = threadIdx.x;
    for (int idx = tid; idx < 16 * 64; idx += 256) {
        int k = idx >> 6, l = idx & 63;
        sW[idx] = (l < 32) ? W2p[k * 32 + l] : W2n[k * 32 + (l - 32)];
    }
    if (tid < 16) { sb1p[tid] = b1p[tid]; sb1n[tid] = b1n[tid]; }
    __syncthreads();

    int t64 = tid & 63;
    int node = blockIdx.x * 4 + (tid >> 6);
    if (node >= n) return;

    const float* ap = g_ap1 + (size_t)node * 16;
    const float* an = g_an1 + (size_t)node * 16;
    float acc = 0.f;
#pragma unroll
    for (int k = 0; k < 16; k++) {
        float hv = relu(__ldg(&ap[k]) + sb1p[k]) - relu(__ldg(&an[k]) + sb1n[k]);
        acc += hv * sW[k * 64 + t64];
    }
    int f = t64 & 31;
    if (t64 < 32) {
        float d = g_dinvp[node];
        g_hp2[node * 32 + f] = acc;
        g_ap2[node * 32 + f] = acc * d * d;
    } else {
        float d = g_dinvn[node];
        g_hn2[node * 32 + f] = acc;
        g_an2[node * 32 + f] = acc * d * d;
    }
}

// Scatter layer 2: 8 lanes (one float4 each) per edge -> 4 edges/warp.
__global__ void k_scatter2(const int* __restrict__ ep, const int* __restrict__ en, int E) {
    int i = blockIdx.x * blockDim.x + threadIdx.x;
    int slot = i >> 3, q = i & 7;
    const int* el; const float* wt; const float* h; float* agg; int e;
    if (slot < E)          { el = ep; wt = g_wp; h = g_hp2; agg = g_ap2; e = slot; }
    else if (slot < 2 * E) { el = en; wt = g_wn; h = g_hn2; agg = g_an2; e = slot - E; }
    else return;

    int src = __ldg(&el[e]);
    int dst = __ldg(&el[E + e]);
    float w = __ldg(&wt[e]);
    float4 v = __ldg(((const float4*)h) + (size_t)src * 8 + q);
    red_add_v4(agg + (size_t)dst * 32 + q * 4, v.x * w, v.y * w, v.z * w, v.w * w);
}

// Epilogue: z = relu(ap2+b2p) - relu(an2+b2n); log_softmax over 32 classes.
__global__ void k_final(const float* __restrict__ b2p, const float* __restrict__ b2n,
                        float* __restrict__ out, int n) {
    int tid  = threadIdx.x;
    int lane = tid & 31;
    int node = blockIdx.x * 8 + (tid >> 5);
    if (node >= n) return;

    float z = relu(g_ap2[node * 32 + lane] + __ldg(&b2p[lane]))
            - relu(g_an2[node * 32 + lane] + __ldg(&b2n[lane]));

    float m = z;
#pragma unroll
    for (int o = 16; o > 0; o >>= 1) m = fmaxf(m, __shfl_xor_sync(0xFFFFFFFF, m, o));
    float ex = expf(z - m);
    float s = ex;
#pragma unroll
    for (int o = 16; o > 0; o >>= 1) s += __shfl_xor_sync(0xFFFFFFFF, s, o);

    out[(size_t)node * 32 + lane] = z - m - logf(s);
}

// ---------------- launch ----------------------------------------------------
extern "C" void kernel_launch(void* const* d_in, const int* in_sizes, int n_in,
                              void* d_out, int out_size) {
    const float* x   = (const float*)d_in[0];
    const int*   ep  = (const int*)  d_in[1];
    const int*   en  = (const int*)  d_in[2];
    const float* W1p = (const float*)d_in[3];
    const float* b1p = (const float*)d_in[4];
    const float* W1n = (const float*)d_in[5];
    const float* b1n = (const float*)d_in[6];
    const float* W2p = (const float*)d_in[7];
    const float* b2p = (const float*)d_in[8];
    const float* W2n = (const float*)d_in[9];
    const float* b2n = (const float*)d_in[10];
    float* out = (float*)d_out;

    int n = in_sizes[0] / 128;     // 100000
    int E = in_sizes[1] / 2;       // 3200000

    int nb_n  = (n + 255) / 256;
    int nb_2e = (2 * E + 255) / 256;
    int nb_s1 = (2 * E * 4 + 255) / 256;   // 4 threads per edge
    int nb_s2 = (2 * E * 8 + 255) / 256;   // 8 threads per edge

    k_zero_deg <<<nb_n, 256>>>(n);
    k_count_deg<<<nb_2e, 256>>>(ep, en, E);
    k_dinv     <<<nb_n, 256>>>(n);
    k_norm     <<<nb_2e, 256>>>(ep, en, E);
    k_gemm1    <<<(n + 31) / 32, 256>>>(x, W1p, W1n, n);
    k_scatter1 <<<nb_s1, 256>>>(ep, en, E);
    k_gemm2    <<<(n + 3) / 4, 256>>>(W2p, W2n, b1p, b1n, n);
    k_scatter2 <<<nb_s2, 256>>>(ep, en, E);
    k_final    <<<(n + 7) / 8, 256>>>(b2p, b2n, out, n);
}

// round 5
// speedup vs baseline: 1.7809x; 1.2157x over previous
#include <cuda_runtime.h>
#include <cuda_bf16.h>

#define N_MAX 100000
#define E_MAX 3200000
#define NBLK_MAX 1024   // ceil(N_MAX/256) = 391 fits

// ---------------- scratch (device globals; no allocation allowed) ----------
__device__ int   g_degp[N_MAX];
__device__ int   g_degn[N_MAX];
__device__ float g_dinvp[N_MAX];
__device__ float g_dinvn[N_MAX];

__device__ int   g_bsump[NBLK_MAX];
__device__ int   g_bsumn[NBLK_MAX];
__device__ int   g_boffp[NBLK_MAX];
__device__ int   g_boffn[NBLK_MAX];
__device__ int   g_offp[N_MAX];
__device__ int   g_offn[N_MAX];
__device__ int   g_curp[N_MAX];
__device__ int   g_curn[N_MAX];

__device__ int2  g_packp[E_MAX];      // CSR-by-dst: {src, w as bits}
__device__ int2  g_packn[E_MAX];

__device__ float g_hp1[N_MAX * 16];   // x @ W1p
__device__ float g_hn1[N_MAX * 16];
__device__ float g_ap1[N_MAX * 16];   // relu(agg_p + b1p)
__device__ float g_an1[N_MAX * 16];   // relu(agg_n + b1n)

__device__ float g_hp2[N_MAX * 32];
__device__ float g_hn2[N_MAX * 32];

__device__ __forceinline__ float relu(float x) { return x > 0.f ? x : 0.f; }

// ---------------- degree / scan / CSR build ---------------------------------
__global__ void k_zero_deg(int n) {
    int i = blockIdx.x * blockDim.x + threadIdx.x;
    if (i < n) { g_degp[i] = 0; g_degn[i] = 0; }
}

__global__ void k_count_deg(const int* __restrict__ ep, const int* __restrict__ en, int E) {
    int i = blockIdx.x * blockDim.x + threadIdx.x;
    if (i < E) {
        atomicAdd(&g_degp[ep[E + i]], 1);
    } else if (i < 2 * E) {
        atomicAdd(&g_degn[en[E + (i - E)]], 1);
    }
}

__global__ void k_dinv(int n) {
    int i = blockIdx.x * blockDim.x + threadIdx.x;
    if (i < n) {
        g_dinvp[i] = rsqrtf((float)g_degp[i] + 1.0f);  // +1 self loop
        g_dinvn[i] = rsqrtf((float)g_degn[i] + 1.0f);
    }
}

// per-256-block degree sums
__global__ void k_scan1(int n) {
    __shared__ int s[256];
    int b = blockIdx.x, t = threadIdx.x, i = b * 256 + t;
    s[t] = (i < n) ? g_degp[i] : 0; __syncthreads();
    for (int d = 128; d > 0; d >>= 1) { if (t < d) s[t] += s[t + d]; __syncthreads(); }
    if (t == 0) g_bsump[b] = s[0];
    __syncthreads();
    s[t] = (i < n) ? g_degn[i] : 0; __syncthreads();
    for (int d = 128; d > 0; d >>= 1) { if (t < d) s[t] += s[t + d]; __syncthreads(); }
    if (t == 0) g_bsumn[b] = s[0];
}

// scan the block sums (one block of NBLK_MAX threads)
__global__ void k_scan2(int nb) {
    __shared__ int s[NBLK_MAX];
    int t = threadIdx.x;
    s[t] = (t < nb) ? g_bsump[t] : 0; __syncthreads();
    for (int d = 1; d < NBLK_MAX; d <<= 1) {
        int v = (t >= d) ? s[t - d] : 0; __syncthreads();
        s[t] += v; __syncthreads();
    }
    if (t < nb) g_boffp[t] = s[t] - g_bsump[t];
    __syncthreads();
    s[t] = (t < nb) ? g_bsumn[t] : 0; __syncthreads();
    for (int d = 1; d < NBLK_MAX; d <<= 1) {
        int v = (t >= d) ? s[t - d] : 0; __syncthreads();
        s[t] += v; __syncthreads();
    }
    if (t < nb) g_boffn[t] = s[t] - g_bsumn[t];
}

// per-node exclusive offsets + cursor init
__global__ void k_scan3(int n) {
    __shared__ int s[256];
    int b = blockIdx.x, t = threadIdx.x, i = b * 256 + t;
    int vp = (i < n) ? g_degp[i] : 0;
    s[t] = vp; __syncthreads();
    for (int d = 1; d < 256; d <<= 1) {
        int v = (t >= d) ? s[t - d] : 0; __syncthreads();
        s[t] += v; __syncthreads();
    }
    if (i < n) { int o = s[t] - vp + g_boffp[b]; g_offp[i] = o; g_curp[i] = o; }
    __syncthreads();
    int vn = (i < n) ? g_degn[i] : 0;
    s[t] = vn; __syncthreads();
    for (int d = 1; d < 256; d <<= 1) {
        int v = (t >= d) ? s[t - d] : 0; __syncthreads();
        s[t] += v; __syncthreads();
    }
    if (i < n) { int o = s[t] - vn + g_boffn[b]; g_offn[i] = o; g_curn[i] = o; }
}

// permute edges into CSR-by-dst slots; fuse norm computation here
__global__ void k_permute(const int* __restrict__ ep, const int* __restrict__ en, int E) {
    int i = blockIdx.x * blockDim.x + threadIdx.x;
    if (i < E) {
        int src = __ldg(&ep[i]), dst = __ldg(&ep[E + i]);
        float w = g_dinvp[src] * g_dinvp[dst];
        int slot = atomicAdd(&g_curp[dst], 1);
        g_packp[slot] = make_int2(src, __float_as_int(w));
    } else if (i < 2 * E) {
        int e = i - E;
        int src = __ldg(&en[e]), dst = __ldg(&en[E + e]);
        float w = g_dinvn[src] * g_dinvn[dst];
        int slot = atomicAdd(&g_curn[dst], 1);
        g_packn[slot] = make_int2(src, __float_as_int(w));
    }
}

// ---------------- GEMM 1 -----------------------------------------------------
// h = x[100k,128] @ [W1p | W1n]. Warp processes 4 nodes; lane = output feature
// (0-15 pos, 16-31 neg). W transposed in smem, reused across 4 nodes.
__global__ void k_gemm1(const float* __restrict__ x,
                        const float* __restrict__ W1p, const float* __restrict__ W1n,
                        int n) {
    __shared__ float sWt[32 * 132];
    int tid = threadIdx.x;
    for (int idx = tid; idx < 128 * 32; idx += 256) {
        int k = idx & 127, f = idx >> 7;
        sWt[f * 132 + k] = (f < 16) ? W1p[k * 16 + f] : W1n[k * 16 + (f - 16)];
    }
    __syncthreads();

    int lane = tid & 31;
    int nb = (blockIdx.x * 8 + (tid >> 5)) * 4;
    if (nb >= n) return;

    const float4* x0 = (const float4*)(x + (size_t)nb * 128);
    const float4* x1 = (nb + 1 < n) ? x0 + 32 : x0;
    const float4* x2 = (nb + 2 < n) ? x0 + 64 : x0;
    const float4* x3 = (nb + 3 < n) ? x0 + 96 : x0;

    float acc0 = 0.f, acc1 = 0.f, acc2 = 0.f, acc3 = 0.f;
#pragma unroll
    for (int k4 = 0; k4 < 32; k4++) {
        float4 w = *(const float4*)&sWt[lane * 132 + k4 * 4];
        float4 a = __ldg(&x0[k4]);
        float4 b = __ldg(&x1[k4]);
        float4 c = __ldg(&x2[k4]);
        float4 d = __ldg(&x3[k4]);
        acc0 += a.x * w.x + a.y * w.y + a.z * w.z + a.w * w.w;
        acc1 += b.x * w.x + b.y * w.y + b.z * w.z + b.w * w.w;
        acc2 += c.x * w.x + c.y * w.y + c.z * w.z + c.w * w.w;
        acc3 += d.x * w.x + d.y * w.y + d.z * w.z + d.w * w.w;
    }

    float accs[4] = {acc0, acc1, acc2, acc3};
    int f = lane & 15;
#pragma unroll
    for (int j = 0; j < 4; j++) {
        int node = nb + j;
        if (node >= n) break;
        if (lane < 16) g_hp1[node * 16 + f] = accs[j];
        else           g_hn1[node * 16 + f] = accs[j];
    }
}

// ---------------- layer-1 aggregation (CSR gather, no atomics) ---------------
// Warp per node: lanes 0-15 pos features, 16-31 neg features. Each half-warp
// reads one 64B h[src] row per edge, coalesced. Fuses self-loop + bias + relu.
__global__ void k_agg1(const float* __restrict__ b1p, const float* __restrict__ b1n,
                       int n) {
    int tid = threadIdx.x, lane = tid & 31;
    int node = blockIdx.x * 8 + (tid >> 5);
    if (node >= n) return;

    bool pos = lane < 16;
    int f = lane & 15;
    const int2*  pack = pos ? g_packp : g_packn;
    const float* h    = pos ? g_hp1   : g_hn1;
    const int*   off  = pos ? g_offp  : g_offn;
    const int*   deg  = pos ? g_degp  : g_degn;
    const float* dinv = pos ? g_dinvp : g_dinvn;

    int row = __ldg(&off[node]);
    int end = row + __ldg(&deg[node]);

    float acc = 0.f;
    int e = row;
    for (; e + 1 < end; e += 2) {
        int2 p0 = __ldg(&pack[e]);
        int2 p1 = __ldg(&pack[e + 1]);
        float v0 = __ldg(&h[(size_t)p0.x * 16 + f]);
        float v1 = __ldg(&h[(size_t)p1.x * 16 + f]);
        acc += v0 * __int_as_float(p0.y) + v1 * __int_as_float(p1.y);
    }
    if (e < end) {
        int2 p0 = __ldg(&pack[e]);
        acc += __ldg(&h[(size_t)p0.x * 16 + f]) * __int_as_float(p0.y);
    }

    float d = __ldg(&dinv[node]);
    acc += __ldg(&h[(size_t)node * 16 + f]) * d * d;   // self loop
    float b = pos ? __ldg(&b1p[f]) : __ldg(&b1n[f]);
    float r = relu(acc + b);
    if (pos) g_ap1[(size_t)node * 16 + f] = r;
    else     g_an1[(size_t)node * 16 + f] = r;
}

// ---------------- GEMM 2 -----------------------------------------------------
// h1 = ap1 - an1 (relu+bias already applied), then h1 @ [W2p | W2n].
__global__ void k_gemm2(const float* __restrict__ W2p, const float* __restrict__ W2n,
                        int n) {
    __shared__ float sW[16 * 64];
    int tid = threadIdx.x;
    for (int idx = tid; idx < 16 * 64; idx += 256) {
        int k = idx >> 6, l = idx & 63;
        sW[idx] = (l < 32) ? W2p[k * 32 + l] : W2n[k * 32 + (l - 32)];
    }
    __syncthreads();

    int t64 = tid & 63;
    int node = blockIdx.x * 4 + (tid >> 6);
    if (node >= n) return;

    const float* ap = g_ap1 + (size_t)node * 16;
    const float* an = g_an1 + (size_t)node * 16;
    float acc = 0.f;
#pragma unroll
    for (int k = 0; k < 16; k++) {
        float hv = __ldg(&ap[k]) - __ldg(&an[k]);
        acc += hv * sW[k * 64 + t64];
    }
    int f = t64 & 31;
    if (t64 < 32) g_hp2[node * 32 + f] = acc;
    else          g_hn2[node * 32 + f] = acc;
}

// ---------------- layer-2 aggregation + epilogue (fused) ---------------------
// Warp per node, lane = class. Pos and neg CSR gathers (128B coalesced rows),
// self loops, biases, relu-combine, then warp log_softmax.
__global__ void k_agg2(const float* __restrict__ b2p, const float* __restrict__ b2n,
                       float* __restrict__ out, int n) {
    int tid = threadIdx.x, lane = tid & 31;
    int node = blockIdx.x * 8 + (tid >> 5);
    if (node >= n) return;

    float accp = 0.f;
    {
        int row = __ldg(&g_offp[node]);
        int end = row + __ldg(&g_degp[node]);
        int e = row;
        for (; e + 1 < end; e += 2) {
            int2 p0 = __ldg(&g_packp[e]);
            int2 p1 = __ldg(&g_packp[e + 1]);
            float v0 = __ldg(&g_hp2[(size_t)p0.x * 32 + lane]);
            float v1 = __ldg(&g_hp2[(size_t)p1.x * 32 + lane]);
            accp += v0 * __int_as_float(p0.y) + v1 * __int_as_float(p1.y);
        }
        if (e < end) {
            int2 p0 = __ldg(&g_packp[e]);
            accp += __ldg(&g_hp2[(size_t)p0.x * 32 + lane]) * __int_as_float(p0.y);
        }
        float d = __ldg(&g_dinvp[node]);
        accp += __ldg(&g_hp2[(size_t)node * 32 + lane]) * d * d;
    }

    float accn = 0.f;
    {
        int row = __ldg(&g_offn[node]);
        int end = row + __ldg(&g_degn[node]);
        int e = row;
        for (; e + 1 < end; e += 2) {
            int2 p0 = __ldg(&g_packn[e]);
            int2 p1 = __ldg(&g_packn[e + 1]);
            float v0 = __ldg(&g_hn2[(size_t)p0.x * 32 + lane]);
            float v1 = __ldg(&g_hn2[(size_t)p1.x * 32 + lane]);
            accn += v0 * __int_as_float(p0.y) + v1 * __int_as_float(p1.y);
        }
        if (e < end) {
            int2 p0 = __ldg(&g_packn[e]);
            accn += __ldg(&g_hn2[(size_t)p0.x * 32 + lane]) * __int_as_float(p0.y);
        }
        float d = __ldg(&g_dinvn[node]);
        accn += __ldg(&g_hn2[(size_t)node * 32 + lane]) * d * d;
    }

    float z = relu(accp + __ldg(&b2p[lane])) - relu(accn + __ldg(&b2n[lane]));

    float m = z;
#pragma unroll
    for (int o = 16; o > 0; o >>= 1) m = fmaxf(m, __shfl_xor_sync(0xFFFFFFFF, m, o));
    float ex = expf(z - m);
    float s = ex;
#pragma unroll
    for (int o = 16; o > 0; o >>= 1) s += __shfl_xor_sync(0xFFFFFFFF, s, o);

    out[(size_t)node * 32 + lane] = z - m - logf(s);
}

// ---------------- launch ----------------------------------------------------
extern "C" void kernel_launch(void* const* d_in, const int* in_sizes, int n_in,
                              void* d_out, int out_size) {
    const float* x   = (const float*)d_in[0];
    const int*   ep  = (const int*)  d_in[1];
    const int*   en  = (const int*)  d_in[2];
    const float* W1p = (const float*)d_in[3];
    const float* b1p = (const float*)d_in[4];
    const float* W1n = (const float*)d_in[5];
    const float* b1n = (const float*)d_in[6];
    const float* W2p = (const float*)d_in[7];
    const float* b2p = (const float*)d_in[8];
    const float* W2n = (const float*)d_in[9];
    const float* b2n = (const float*)d_in[10];
    float* out = (float*)d_out;

    int n = in_sizes[0] / 128;     // 100000
    int E = in_sizes[1] / 2;       // 3200000

    int nb_n  = (n + 255) / 256;   // 391
    int nb_2e = (2 * E + 255) / 256;

    k_zero_deg <<<nb_n, 256>>>(n);
    k_count_deg<<<nb_2e, 256>>>(ep, en, E);
    k_dinv     <<<nb_n, 256>>>(n);
    k_scan1    <<<nb_n, 256>>>(n);
    k_scan2    <<<1, NBLK_MAX>>>(nb_n);
    k_scan3    <<<nb_n, 256>>>(n);
    k_permute  <<<nb_2e, 256>>>(ep, en, E);
    k_gemm1    <<<(n + 31) / 32, 256>>>(x, W1p, W1n, n);
    k_agg1     <<<(n + 7) / 8, 256>>>(b1p, b1n, n);
    k_gemm2    <<<(n + 3) / 4, 256>>>(W2p, W2n, n);
    k_agg2     <<<(n + 7) / 8, 256>>>(b2p, b2n, out, n);
}